// round 2
// baseline (speedup 1.0000x reference)
#include <cuda_runtime.h>
#include <math.h>

// Problem constants
#define BB   2
#define NSEQ 2048
#define CDIM 1024
#define HEADS 16
#define HD   64
#define NG   8
#define KG   128      // Cin per group
#define QKV_OUT 384   // per-group qkv out cols (3*1024/8)

// Scratch (device globals; no allocation allowed)
__device__ float g_q[BB*HEADS*NSEQ*HD];
__device__ float g_k[BB*HEADS*NSEQ*HD];
__device__ float g_v[BB*HEADS*NSEQ*HD];
__device__ float g_attn[BB*NSEQ*CDIM];

// ---------------------------------------------------------------------------
// QKV grouped GEMM: per group g: X[4096,128] x W[128,384] -> scatter to q/k/v
// grid (64, 6, 8), block 256 (16x16 threads, 4x4 outputs each)
// ---------------------------------------------------------------------------
__global__ void __launch_bounds__(256)
qkv_kernel(const float* __restrict__ x, const float* __restrict__ w)
{
    __shared__ float Xs[64*36];   // [row][k], padded stride 36
    __shared__ float Ws[32*64];   // [k][col]

    const int mt = blockIdx.x, ct = blockIdx.y, g = blockIdx.z;
    const int tid = threadIdx.x;
    const int ty = tid >> 4, tx = tid & 15;
    const int m0 = mt * 64;

    float acc[4][4];
#pragma unroll
    for (int i = 0; i < 4; i++)
#pragma unroll
        for (int j = 0; j < 4; j++) acc[i][j] = 0.f;

    const float* xg = x + (size_t)m0 * CDIM + g * KG;
    const float* wg = w + (size_t)g * KG * QKV_OUT + ct * 64;

    const int lr = tid >> 2;        // 0..63 row for X load
    const int lk = (tid & 3) * 8;   // k offset
    const int wk = tid >> 3;        // 0..31 k row for W load
    const int wc = (tid & 7) * 8;   // col offset

    for (int k0 = 0; k0 < KG; k0 += 32) {
        __syncthreads();
        {
            const float* src = xg + (size_t)lr * CDIM + k0 + lk;
            float4 v0 = *(const float4*)src;
            float4 v1 = *(const float4*)(src + 4);
            float* d = &Xs[lr * 36 + lk];
            d[0]=v0.x; d[1]=v0.y; d[2]=v0.z; d[3]=v0.w;
            d[4]=v1.x; d[5]=v1.y; d[6]=v1.z; d[7]=v1.w;
        }
        {
            const float* src = wg + (size_t)(k0 + wk) * QKV_OUT + wc;
            float4 v0 = *(const float4*)src;
            float4 v1 = *(const float4*)(src + 4);
            float* d = &Ws[wk * 64 + wc];
            *(float4*)d = v0; *(float4*)(d + 4) = v1;
        }
        __syncthreads();
#pragma unroll
        for (int kk = 0; kk < 32; kk++) {
            float4 bf = *(const float4*)&Ws[kk * 64 + tx * 4];
            float a0 = Xs[(ty*4+0)*36 + kk];
            float a1 = Xs[(ty*4+1)*36 + kk];
            float a2 = Xs[(ty*4+2)*36 + kk];
            float a3 = Xs[(ty*4+3)*36 + kk];
            acc[0][0] += a0*bf.x; acc[0][1] += a0*bf.y; acc[0][2] += a0*bf.z; acc[0][3] += a0*bf.w;
            acc[1][0] += a1*bf.x; acc[1][1] += a1*bf.y; acc[1][2] += a1*bf.z; acc[1][3] += a1*bf.w;
            acc[2][0] += a2*bf.x; acc[2][1] += a2*bf.y; acc[2][2] += a2*bf.z; acc[2][3] += a2*bf.w;
            acc[3][0] += a3*bf.x; acc[3][1] += a3*bf.y; acc[3][2] += a3*bf.z; acc[3][3] += a3*bf.w;
        }
    }

    // scatter: output channel o = g*384 + ct*64 + 4tx + j maps to (t,h,d)
    const int obase = g * QKV_OUT + ct * 64 + tx * 4;   // 4-aligned; j in [0,4) stays in same (t,h)
    const int t = obase >> 10;
    const int rem = obase & 1023;
    const int h = rem >> 6;
    const int d0 = rem & 63;
#pragma unroll
    for (int i = 0; i < 4; i++) {
        int m = m0 + ty * 4 + i;
        int b = m >> 11, n = m & 2047;
        size_t dst = (((size_t)b * HEADS + h) * NSEQ + n) * HD + d0;
        float4 v;
        if (t == 0) {   // q: pre-apply 1/sqrt(D)
            v = make_float4(acc[i][0]*0.125f, acc[i][1]*0.125f, acc[i][2]*0.125f, acc[i][3]*0.125f);
            *(float4*)&g_q[dst] = v;
        } else if (t == 1) {
            v = make_float4(acc[i][0], acc[i][1], acc[i][2], acc[i][3]);
            *(float4*)&g_k[dst] = v;
        } else {
            v = make_float4(acc[i][0], acc[i][1], acc[i][2], acc[i][3]);
            *(float4*)&g_v[dst] = v;
        }
    }
}

// ---------------------------------------------------------------------------
// Flash attention, fp32. grid (32 qtiles, 32 bh), block 256 (16x16).
// Q tile 64x64 resident (transposed), stream K/V tiles of 64.
// smem: Qt(16K) + KP(16K, K^T then P alias) + Vs(16K) = 48KB (static max)
// ---------------------------------------------------------------------------
__device__ __forceinline__ float rmax16(float v) {
#pragma unroll
    for (int off = 8; off > 0; off >>= 1)
        v = fmaxf(v, __shfl_xor_sync(0xffffffffu, v, off, 16));
    return v;
}
__device__ __forceinline__ float rsum16(float v) {
#pragma unroll
    for (int off = 8; off > 0; off >>= 1)
        v += __shfl_xor_sync(0xffffffffu, v, off, 16);
    return v;
}

__global__ void __launch_bounds__(256)
attn_kernel()
{
    __shared__ float Qt[64*64];   // [d][row]
    __shared__ float KP[64*64];   // K^T [d][key], then P [row][key]
    __shared__ float Vs[64*64];   // [key][d]

    const int qt = blockIdx.x;    // 0..31
    const int bh = blockIdx.y;    // 0..31  (b*16+h)
    const int tid = threadIdx.x;
    const int ty = tid >> 4, tx = tid & 15;

    const float* Qg = g_q + (size_t)bh * NSEQ * HD + (size_t)qt * 64 * HD;
    const float* Kg = g_k + (size_t)bh * NSEQ * HD;
    const float* Vg = g_v + (size_t)bh * NSEQ * HD;

    const int lr = tid >> 2;        // row (query/key) for transposed loads
    const int ld = (tid & 3) * 16;  // d chunk

    // load Q transposed: Qt[d][row]
    {
        const float* src = Qg + (size_t)lr * HD + ld;
#pragma unroll
        for (int u = 0; u < 4; u++) {
            float4 v = *(const float4*)(src + u * 4);
            int dd = ld + u * 4;
            Qt[(dd+0)*64 + lr] = v.x;
            Qt[(dd+1)*64 + lr] = v.y;
            Qt[(dd+2)*64 + lr] = v.z;
            Qt[(dd+3)*64 + lr] = v.w;
        }
    }

    float m[4], l[4], o[4][4];
#pragma unroll
    for (int i = 0; i < 4; i++) {
        m[i] = -1e30f; l[i] = 0.f;
#pragma unroll
        for (int j = 0; j < 4; j++) o[i][j] = 0.f;
    }

    for (int kt = 0; kt < NSEQ / 64; kt++) {
        __syncthreads();   // prior PV done reading KP/Vs
        // load K transposed: KP[d][key]
        {
            const float* src = Kg + (size_t)(kt * 64 + lr) * HD + ld;
#pragma unroll
            for (int u = 0; u < 4; u++) {
                float4 v = *(const float4*)(src + u * 4);
                int dd = ld + u * 4;
                KP[(dd+0)*64 + lr] = v.x;
                KP[(dd+1)*64 + lr] = v.y;
                KP[(dd+2)*64 + lr] = v.z;
                KP[(dd+3)*64 + lr] = v.w;
            }
        }
        // load V natural, straight float4 copy
        {
            const float4* src = (const float4*)(Vg + (size_t)kt * 64 * HD);
            float4* dst = (float4*)Vs;
#pragma unroll
            for (int u = 0; u < 4; u++) dst[u * 256 + tid] = src[u * 256 + tid];
        }
        __syncthreads();

        // S = Q K^T  (both operands [d][*] in smem, LDS.128 fragments)
        float s[4][4];
#pragma unroll
        for (int i = 0; i < 4; i++)
#pragma unroll
            for (int j = 0; j < 4; j++) s[i][j] = 0.f;

#pragma unroll 16
        for (int d = 0; d < HD; d++) {
            float4 af = *(const float4*)&Qt[d * 64 + ty * 4];
            float4 bf = *(const float4*)&KP[d * 64 + tx * 4];
            s[0][0] += af.x*bf.x; s[0][1] += af.x*bf.y; s[0][2] += af.x*bf.z; s[0][3] += af.x*bf.w;
            s[1][0] += af.y*bf.x; s[1][1] += af.y*bf.y; s[1][2] += af.y*bf.z; s[1][3] += af.y*bf.w;
            s[2][0] += af.z*bf.x; s[2][1] += af.z*bf.y; s[2][2] += af.z*bf.z; s[2][3] += af.z*bf.w;
            s[3][0] += af.w*bf.x; s[3][1] += af.w*bf.y; s[3][2] += af.w*bf.z; s[3][3] += af.w*bf.w;
        }

        // online softmax update (row-wise; 16 tx threads share a row)
#pragma unroll
        for (int i = 0; i < 4; i++) {
            float tmax = fmaxf(fmaxf(s[i][0], s[i][1]), fmaxf(s[i][2], s[i][3]));
            tmax = rmax16(tmax);
            float nm = fmaxf(m[i], tmax);
            float alpha = __expf(m[i] - nm);
            float ps = 0.f;
#pragma unroll
            for (int j = 0; j < 4; j++) {
                float p = __expf(s[i][j] - nm);
                s[i][j] = p;
                ps += p;
            }
            ps = rsum16(ps);
            l[i] = l[i] * alpha + ps;
            m[i] = nm;
#pragma unroll
            for (int j = 0; j < 4; j++) o[i][j] *= alpha;
        }

        __syncthreads();   // everyone done reading K^T before P overwrites KP
        // write P natural: KP[row][key]
#pragma unroll
        for (int i = 0; i < 4; i++)
#pragma unroll
            for (int j = 0; j < 4; j++)
                KP[(ty*4+i)*64 + tx*4+j] = s[i][j];
        __syncthreads();

        // O += P V
#pragma unroll 16
        for (int k = 0; k < 64; k++) {
            float4 bf = *(const float4*)&Vs[k * 64 + tx * 4];
            float a0 = KP[(ty*4+0)*64 + k];
            float a1 = KP[(ty*4+1)*64 + k];
            float a2 = KP[(ty*4+2)*64 + k];
            float a3 = KP[(ty*4+3)*64 + k];
            o[0][0] += a0*bf.x; o[0][1] += a0*bf.y; o[0][2] += a0*bf.z; o[0][3] += a0*bf.w;
            o[1][0] += a1*bf.x; o[1][1] += a1*bf.y; o[1][2] += a1*bf.z; o[1][3] += a1*bf.w;
            o[2][0] += a2*bf.x; o[2][1] += a2*bf.y; o[2][2] += a2*bf.z; o[2][3] += a2*bf.w;
            o[3][0] += a3*bf.x; o[3][1] += a3*bf.y; o[3][2] += a3*bf.z; o[3][3] += a3*bf.w;
        }
    }

    // epilogue: normalize and store to [B, N, C] layout (channel = h*64+d)
    const int b = bh >> 4, h = bh & 15;
#pragma unroll
    for (int i = 0; i < 4; i++) {
        float inv = 1.f / l[i];
        int n = qt * 64 + ty * 4 + i;
        float* dst = g_attn + ((size_t)b * NSEQ + n) * CDIM + h * HD + tx * 4;
        *(float4*)dst = make_float4(o[i][0]*inv, o[i][1]*inv, o[i][2]*inv, o[i][3]*inv);
    }
}

// ---------------------------------------------------------------------------
// Proj grouped GEMM: per group g: attn[4096,128] x W[128,128] + bias -> out
// grid (64, 2, 8), block 256
// ---------------------------------------------------------------------------
__global__ void __launch_bounds__(256)
proj_kernel(const float* __restrict__ w, const float* __restrict__ bias,
            float* __restrict__ out)
{
    __shared__ float Xs[64*36];
    __shared__ float Ws[32*64];

    const int mt = blockIdx.x, ct = blockIdx.y, g = blockIdx.z;
    const int tid = threadIdx.x;
    const int ty = tid >> 4, tx = tid & 15;
    const int m0 = mt * 64;

    float acc[4][4];
#pragma unroll
    for (int i = 0; i < 4; i++)
#pragma unroll
        for (int j = 0; j < 4; j++) acc[i][j] = 0.f;

    const float* xg = g_attn + (size_t)m0 * CDIM + g * KG;
    const float* wg = w + (size_t)g * KG * KG + ct * 64;

    const int lr = tid >> 2;
    const int lk = (tid & 3) * 8;
    const int wk = tid >> 3;
    const int wc = (tid & 7) * 8;

    for (int k0 = 0; k0 < KG; k0 += 32) {
        __syncthreads();
        {
            const float* src = xg + (size_t)lr * CDIM + k0 + lk;
            float4 v0 = *(const float4*)src;
            float4 v1 = *(const float4*)(src + 4);
            float* d = &Xs[lr * 36 + lk];
            d[0]=v0.x; d[1]=v0.y; d[2]=v0.z; d[3]=v0.w;
            d[4]=v1.x; d[5]=v1.y; d[6]=v1.z; d[7]=v1.w;
        }
        {
            const float* src = wg + (size_t)(k0 + wk) * KG + wc;
            float4 v0 = *(const float4*)src;
            float4 v1 = *(const float4*)(src + 4);
            float* d = &Ws[wk * 64 + wc];
            *(float4*)d = v0; *(float4*)(d + 4) = v1;
        }
        __syncthreads();
#pragma unroll
        for (int kk = 0; kk < 32; kk++) {
            float4 bf = *(const float4*)&Ws[kk * 64 + tx * 4];
            float a0 = Xs[(ty*4+0)*36 + kk];
            float a1 = Xs[(ty*4+1)*36 + kk];
            float a2 = Xs[(ty*4+2)*36 + kk];
            float a3 = Xs[(ty*4+3)*36 + kk];
            acc[0][0] += a0*bf.x; acc[0][1] += a0*bf.y; acc[0][2] += a0*bf.z; acc[0][3] += a0*bf.w;
            acc[1][0] += a1*bf.x; acc[1][1] += a1*bf.y; acc[1][2] += a1*bf.z; acc[1][3] += a1*bf.w;
            acc[2][0] += a2*bf.x; acc[2][1] += a2*bf.y; acc[2][2] += a2*bf.z; acc[2][3] += a2*bf.w;
            acc[3][0] += a3*bf.x; acc[3][1] += a3*bf.y; acc[3][2] += a3*bf.z; acc[3][3] += a3*bf.w;
        }
    }

    const int obase = g * KG + ct * 64 + tx * 4;
    float4 bv = *(const float4*)&bias[obase];
#pragma unroll
    for (int i = 0; i < 4; i++) {
        int mrow = m0 + ty * 4 + i;
        float4 v = make_float4(acc[i][0]+bv.x, acc[i][1]+bv.y, acc[i][2]+bv.z, acc[i][3]+bv.w);
        *(float4*)&out[(size_t)mrow * CDIM + obase] = v;
    }
}

// ---------------------------------------------------------------------------
extern "C" void kernel_launch(void* const* d_in, const int* in_sizes, int n_in,
                              void* d_out, int out_size)
{
    const float* x      = (const float*)d_in[0];   // [2,2048,1024]
    const float* w_qkv  = (const float*)d_in[1];   // [8,128,384]
    const float* w_proj = (const float*)d_in[2];   // [8,128,128]
    const float* b_proj = (const float*)d_in[3];   // [1024]
    float* out = (float*)d_out;                    // [2,2048,1024]

    qkv_kernel<<<dim3(64, 6, 8), 256>>>(x, w_qkv);
    attn_kernel<<<dim3(32, 32), 256>>>();
    proj_kernel<<<dim3(64, 2, 8), 256>>>(w_proj, b_proj, out);
}

// round 4
// speedup vs baseline: 2.2161x; 2.2161x over previous
#include <cuda_runtime.h>
#include <cstdint>
#include <stdint.h>
#include <math.h>

// Problem constants
#define BB   2
#define NSEQ 2048
#define CDIM 1024
#define HEADS 16
#define HD   64
#define NG   8
#define KG   128      // Cin per group
#define QKV_OUT 384   // per-group qkv out cols (3*1024/8)

// Scratch (device globals; no allocation allowed)
__device__ float g_q[BB*HEADS*NSEQ*HD];
__device__ float g_k[BB*HEADS*NSEQ*HD];
__device__ float g_v[BB*HEADS*NSEQ*HD];
__device__ float g_attn[BB*NSEQ*CDIM];

// ---------------------------------------------------------------------------
// QKV grouped GEMM: per group g: X[4096,128] x W[128,384] -> scatter to q/k/v
// grid (64, 6, 8), block 256 (16x16 threads, 4x4 outputs each)   [unchanged]
// ---------------------------------------------------------------------------
__global__ void __launch_bounds__(256)
qkv_kernel(const float* __restrict__ x, const float* __restrict__ w)
{
    __shared__ float Xs[64*36];   // [row][k], padded stride 36
    __shared__ float Ws[32*64];   // [k][col]

    const int mt = blockIdx.x, ct = blockIdx.y, g = blockIdx.z;
    const int tid = threadIdx.x;
    const int ty = tid >> 4, tx = tid & 15;
    const int m0 = mt * 64;

    float acc[4][4];
#pragma unroll
    for (int i = 0; i < 4; i++)
#pragma unroll
        for (int j = 0; j < 4; j++) acc[i][j] = 0.f;

    const float* xg = x + (size_t)m0 * CDIM + g * KG;
    const float* wg = w + (size_t)g * KG * QKV_OUT + ct * 64;

    const int lr = tid >> 2;        // 0..63 row for X load
    const int lk = (tid & 3) * 8;   // k offset
    const int wk = tid >> 3;        // 0..31 k row for W load
    const int wc = (tid & 7) * 8;   // col offset

    for (int k0 = 0; k0 < KG; k0 += 32) {
        __syncthreads();
        {
            const float* src = xg + (size_t)lr * CDIM + k0 + lk;
            float4 v0 = *(const float4*)src;
            float4 v1 = *(const float4*)(src + 4);
            float* d = &Xs[lr * 36 + lk];
            d[0]=v0.x; d[1]=v0.y; d[2]=v0.z; d[3]=v0.w;
            d[4]=v1.x; d[5]=v1.y; d[6]=v1.z; d[7]=v1.w;
        }
        {
            const float* src = wg + (size_t)(k0 + wk) * QKV_OUT + wc;
            float4 v0 = *(const float4*)src;
            float4 v1 = *(const float4*)(src + 4);
            float* d = &Ws[wk * 64 + wc];
            *(float4*)d = v0; *(float4*)(d + 4) = v1;
        }
        __syncthreads();
#pragma unroll
        for (int kk = 0; kk < 32; kk++) {
            float4 bf = *(const float4*)&Ws[kk * 64 + tx * 4];
            float a0 = Xs[(ty*4+0)*36 + kk];
            float a1 = Xs[(ty*4+1)*36 + kk];
            float a2 = Xs[(ty*4+2)*36 + kk];
            float a3 = Xs[(ty*4+3)*36 + kk];
            acc[0][0] += a0*bf.x; acc[0][1] += a0*bf.y; acc[0][2] += a0*bf.z; acc[0][3] += a0*bf.w;
            acc[1][0] += a1*bf.x; acc[1][1] += a1*bf.y; acc[1][2] += a1*bf.z; acc[1][3] += a1*bf.w;
            acc[2][0] += a2*bf.x; acc[2][1] += a2*bf.y; acc[2][2] += a2*bf.z; acc[2][3] += a2*bf.w;
            acc[3][0] += a3*bf.x; acc[3][1] += a3*bf.y; acc[3][2] += a3*bf.z; acc[3][3] += a3*bf.w;
        }
    }

    const int obase = g * QKV_OUT + ct * 64 + tx * 4;   // 4-aligned
    const int t = obase >> 10;
    const int rem = obase & 1023;
    const int h = rem >> 6;
    const int d0 = rem & 63;
#pragma unroll
    for (int i = 0; i < 4; i++) {
        int m = m0 + ty * 4 + i;
        int b = m >> 11, n = m & 2047;
        size_t dst = (((size_t)b * HEADS + h) * NSEQ + n) * HD + d0;
        float4 v;
        if (t == 0) {   // q: pre-apply 1/sqrt(D)
            v = make_float4(acc[i][0]*0.125f, acc[i][1]*0.125f, acc[i][2]*0.125f, acc[i][3]*0.125f);
            *(float4*)&g_q[dst] = v;
        } else if (t == 1) {
            v = make_float4(acc[i][0], acc[i][1], acc[i][2], acc[i][3]);
            *(float4*)&g_k[dst] = v;
        } else {
            v = make_float4(acc[i][0], acc[i][1], acc[i][2], acc[i][3]);
            *(float4*)&g_v[dst] = v;
        }
    }
}

// ---------------------------------------------------------------------------
// Flash attention with tf32 mma.sync (tensor cores), fp32 softmax.
// grid (32 qtiles, 32 bh), block 128 (4 warps). Each warp: 16 query rows.
// Per key tile (64): S = Q K^T (m16n8k8 tf32), online softmax in regs,
// P C-frag -> A-frag via shuffles, O += P V.
// smem: Ks[64][68] + Vs[64][68] = 34816 B
// ---------------------------------------------------------------------------
#define PADK 68

__device__ __forceinline__ uint32_t f2tf32(float x) {
    uint32_t r;
    asm("cvt.rna.tf32.f32 %0, %1;" : "=r"(r) : "f"(x));
    return r;
}

__device__ __forceinline__ void mma_tf32(float* d, const uint32_t* a, uint32_t b0, uint32_t b1) {
    asm volatile(
        "mma.sync.aligned.m16n8k8.row.col.f32.tf32.tf32.f32 "
        "{%0,%1,%2,%3}, {%4,%5,%6,%7}, {%8,%9}, {%0,%1,%2,%3};"
        : "+f"(d[0]), "+f"(d[1]), "+f"(d[2]), "+f"(d[3])
        : "r"(a[0]), "r"(a[1]), "r"(a[2]), "r"(a[3]), "r"(b0), "r"(b1));
}

__global__ void __launch_bounds__(128)
attn_kernel()
{
    __shared__ float Ks[64 * PADK];   // also used to stage Q in prologue
    __shared__ float Vs[64 * PADK];

    const int qt  = blockIdx.x;          // 0..31
    const int bh  = blockIdx.y;          // 0..31
    const int tid = threadIdx.x;
    const int w   = tid >> 5;            // warp 0..3
    const int lane = tid & 31;
    const int g = lane >> 2;             // 0..7 group
    const int t = lane & 3;              // 0..3 thread-in-group
    const int q0w = w * 16;              // warp's row base within 64-row tile

    const float* Qg = g_q + (size_t)bh * NSEQ * HD + (size_t)qt * 64 * HD;
    const float* Kg = g_k + (size_t)bh * NSEQ * HD;
    const float* Vg = g_v + (size_t)bh * NSEQ * HD;

    // ---- prologue: stage Q (tf32-rounded) into Ks, build A fragments ----
#pragma unroll
    for (int i = 0; i < 8; i++) {
        int idx = i * 128 + tid;             // 0..1023 float4 units
        int r = idx >> 4;
        int c = (idx & 15) * 4;
        float4 v = *(const float4*)(Qg + (size_t)r * HD + c);
        float* d = &Ks[r * PADK + c];
        d[0] = __uint_as_float(f2tf32(v.x));
        d[1] = __uint_as_float(f2tf32(v.y));
        d[2] = __uint_as_float(f2tf32(v.z));
        d[3] = __uint_as_float(f2tf32(v.w));
    }
    __syncthreads();

    uint32_t qa[8][4];
#pragma unroll
    for (int ks = 0; ks < 8; ks++) {
        qa[ks][0] = __float_as_uint(Ks[(q0w + g    ) * PADK + ks*8 + t    ]);
        qa[ks][1] = __float_as_uint(Ks[(q0w + g + 8) * PADK + ks*8 + t    ]);
        qa[ks][2] = __float_as_uint(Ks[(q0w + g    ) * PADK + ks*8 + t + 4]);
        qa[ks][3] = __float_as_uint(Ks[(q0w + g + 8) * PADK + ks*8 + t + 4]);
    }

    // online softmax state: rows (q0w+g) and (q0w+g+8)
    float m0 = -1e30f, m1 = -1e30f, l0 = 0.f, l1 = 0.f;
    float o[8][4];
#pragma unroll
    for (int nb = 0; nb < 8; nb++)
#pragma unroll
        for (int j = 0; j < 4; j++) o[nb][j] = 0.f;

    const int srcA = (lane & 28) | (t >> 1);
    const int srcB = srcA + 2;
    const bool odd = (t & 1);

    for (int kt = 0; kt < NSEQ / 64; kt++) {
        __syncthreads();   // Ks/Vs free (Q frags built / prev tile done)
        // load K and V tiles, tf32-rounded
        const float* Kt = Kg + (size_t)kt * 64 * HD;
        const float* Vt = Vg + (size_t)kt * 64 * HD;
#pragma unroll
        for (int i = 0; i < 8; i++) {
            int idx = i * 128 + tid;
            int r = idx >> 4;
            int c = (idx & 15) * 4;
            float4 v = *(const float4*)(Kt + (size_t)r * HD + c);
            float* d = &Ks[r * PADK + c];
            d[0] = __uint_as_float(f2tf32(v.x));
            d[1] = __uint_as_float(f2tf32(v.y));
            d[2] = __uint_as_float(f2tf32(v.z));
            d[3] = __uint_as_float(f2tf32(v.w));
            float4 u = *(const float4*)(Vt + (size_t)r * HD + c);
            float* e = &Vs[r * PADK + c];
            e[0] = __uint_as_float(f2tf32(u.x));
            e[1] = __uint_as_float(f2tf32(u.y));
            e[2] = __uint_as_float(f2tf32(u.z));
            e[3] = __uint_as_float(f2tf32(u.w));
        }
        __syncthreads();

        // ---- S = Q K^T ----
        float s[8][4];
#pragma unroll
        for (int nb = 0; nb < 8; nb++) {
#pragma unroll
            for (int j = 0; j < 4; j++) s[nb][j] = 0.f;
            const float* kb = &Ks[(nb*8 + g) * PADK];
#pragma unroll
            for (int ks = 0; ks < 8; ks++) {
                uint32_t b0 = __float_as_uint(kb[ks*8 + t]);
                uint32_t b1 = __float_as_uint(kb[ks*8 + t + 4]);
                mma_tf32(s[nb], qa[ks], b0, b1);
            }
        }

        // ---- online softmax (rows g / g+8, spread over 4 lanes) ----
        float mx0 = -1e30f, mx1 = -1e30f;
#pragma unroll
        for (int nb = 0; nb < 8; nb++) {
            mx0 = fmaxf(mx0, fmaxf(s[nb][0], s[nb][1]));
            mx1 = fmaxf(mx1, fmaxf(s[nb][2], s[nb][3]));
        }
        mx0 = fmaxf(mx0, __shfl_xor_sync(0xffffffffu, mx0, 1));
        mx0 = fmaxf(mx0, __shfl_xor_sync(0xffffffffu, mx0, 2));
        mx1 = fmaxf(mx1, __shfl_xor_sync(0xffffffffu, mx1, 1));
        mx1 = fmaxf(mx1, __shfl_xor_sync(0xffffffffu, mx1, 2));

        float nm0 = fmaxf(m0, mx0), nm1 = fmaxf(m1, mx1);
        float al0 = __expf(m0 - nm0), al1 = __expf(m1 - nm1);
        m0 = nm0; m1 = nm1;

        float ps0 = 0.f, ps1 = 0.f;
#pragma unroll
        for (int nb = 0; nb < 8; nb++) {
            float p0 = __uint_as_float(f2tf32(__expf(s[nb][0] - nm0)));
            float p1 = __uint_as_float(f2tf32(__expf(s[nb][1] - nm0)));
            float p2 = __uint_as_float(f2tf32(__expf(s[nb][2] - nm1)));
            float p3 = __uint_as_float(f2tf32(__expf(s[nb][3] - nm1)));
            s[nb][0] = p0; s[nb][1] = p1; s[nb][2] = p2; s[nb][3] = p3;
            ps0 += p0 + p1;
            ps1 += p2 + p3;
        }
        ps0 += __shfl_xor_sync(0xffffffffu, ps0, 1);
        ps0 += __shfl_xor_sync(0xffffffffu, ps0, 2);
        ps1 += __shfl_xor_sync(0xffffffffu, ps1, 1);
        ps1 += __shfl_xor_sync(0xffffffffu, ps1, 2);
        l0 = l0 * al0 + ps0;
        l1 = l1 * al1 + ps1;

#pragma unroll
        for (int nb = 0; nb < 8; nb++) {
            o[nb][0] *= al0; o[nb][1] *= al0;
            o[nb][2] *= al1; o[nb][3] *= al1;
        }

        // ---- O += P V : per k-step, convert P C-frag -> A-frag via shfl ----
#pragma unroll
        for (int ks = 0; ks < 8; ks++) {
            float c0A = __shfl_sync(0xffffffffu, s[ks][0], srcA);
            float c1A = __shfl_sync(0xffffffffu, s[ks][1], srcA);
            float c0B = __shfl_sync(0xffffffffu, s[ks][0], srcB);
            float c1B = __shfl_sync(0xffffffffu, s[ks][1], srcB);
            float c2A = __shfl_sync(0xffffffffu, s[ks][2], srcA);
            float c3A = __shfl_sync(0xffffffffu, s[ks][3], srcA);
            float c2B = __shfl_sync(0xffffffffu, s[ks][2], srcB);
            float c3B = __shfl_sync(0xffffffffu, s[ks][3], srcB);
            uint32_t pa[4];
            pa[0] = __float_as_uint(odd ? c1A : c0A);
            pa[1] = __float_as_uint(odd ? c3A : c2A);
            pa[2] = __float_as_uint(odd ? c1B : c0B);
            pa[3] = __float_as_uint(odd ? c3B : c2B);

            const float* vb0 = &Vs[(ks*8 + t    ) * PADK];
            const float* vb1 = &Vs[(ks*8 + t + 4) * PADK];
#pragma unroll
            for (int nb = 0; nb < 8; nb++) {
                uint32_t b0 = __float_as_uint(vb0[nb*8 + g]);
                uint32_t b1 = __float_as_uint(vb1[nb*8 + g]);
                mma_tf32(o[nb], pa, b0, b1);
            }
        }
    }

    // ---- epilogue: normalize, store to [B, N, C] (channel = h*64+d) ----
    const int b = bh >> 4, h = bh & 15;
    float inv0 = 1.f / l0, inv1 = 1.f / l1;
    int n0 = qt * 64 + q0w + g;
    float* row0 = g_attn + ((size_t)b * NSEQ + n0    ) * CDIM + h * HD;
    float* row1 = g_attn + ((size_t)b * NSEQ + n0 + 8) * CDIM + h * HD;
#pragma unroll
    for (int nb = 0; nb < 8; nb++) {
        int c = nb * 8 + 2 * t;
        *(float2*)&row0[c] = make_float2(o[nb][0] * inv0, o[nb][1] * inv0);
        *(float2*)&row1[c] = make_float2(o[nb][2] * inv1, o[nb][3] * inv1);
    }
}

// ---------------------------------------------------------------------------
// Proj grouped GEMM: per group g: attn[4096,128] x W[128,128] + bias -> out
// grid (64, 2, 8), block 256   [unchanged]
// ---------------------------------------------------------------------------
__global__ void __launch_bounds__(256)
proj_kernel(const float* __restrict__ w, const float* __restrict__ bias,
            float* __restrict__ out)
{
    __shared__ float Xs[64*36];
    __shared__ float Ws[32*64];

    const int mt = blockIdx.x, ct = blockIdx.y, g = blockIdx.z;
    const int tid = threadIdx.x;
    const int ty = tid >> 4, tx = tid & 15;
    const int m0 = mt * 64;

    float acc[4][4];
#pragma unroll
    for (int i = 0; i < 4; i++)
#pragma unroll
        for (int j = 0; j < 4; j++) acc[i][j] = 0.f;

    const float* xg = g_attn + (size_t)m0 * CDIM + g * KG;
    const float* wg = w + (size_t)g * KG * KG + ct * 64;

    const int lr = tid >> 2;
    const int lk = (tid & 3) * 8;
    const int wk = tid >> 3;
    const int wc = (tid & 7) * 8;

    for (int k0 = 0; k0 < KG; k0 += 32) {
        __syncthreads();
        {
            const float* src = xg + (size_t)lr * CDIM + k0 + lk;
            float4 v0 = *(const float4*)src;
            float4 v1 = *(const float4*)(src + 4);
            float* d = &Xs[lr * 36 + lk];
            d[0]=v0.x; d[1]=v0.y; d[2]=v0.z; d[3]=v0.w;
            d[4]=v1.x; d[5]=v1.y; d[6]=v1.z; d[7]=v1.w;
        }
        {
            const float* src = wg + (size_t)(k0 + wk) * KG + wc;
            float4 v0 = *(const float4*)src;
            float4 v1 = *(const float4*)(src + 4);
            float* d = &Ws[wk * 64 + wc];
            *(float4*)d = v0; *(float4*)(d + 4) = v1;
        }
        __syncthreads();
#pragma unroll
        for (int kk = 0; kk < 32; kk++) {
            float4 bf = *(const float4*)&Ws[kk * 64 + tx * 4];
            float a0 = Xs[(ty*4+0)*36 + kk];
            float a1 = Xs[(ty*4+1)*36 + kk];
            float a2 = Xs[(ty*4+2)*36 + kk];
            float a3 = Xs[(ty*4+3)*36 + kk];
            acc[0][0] += a0*bf.x; acc[0][1] += a0*bf.y; acc[0][2] += a0*bf.z; acc[0][3] += a0*bf.w;
            acc[1][0] += a1*bf.x; acc[1][1] += a1*bf.y; acc[1][2] += a1*bf.z; acc[1][3] += a1*bf.w;
            acc[2][0] += a2*bf.x; acc[2][1] += a2*bf.y; acc[2][2] += a2*bf.z; acc[2][3] += a2*bf.w;
            acc[3][0] += a3*bf.x; acc[3][1] += a3*bf.y; acc[3][2] += a3*bf.z; acc[3][3] += a3*bf.w;
        }
    }

    const int obase = g * KG + ct * 64 + tx * 4;
    float4 bv = *(const float4*)&bias[obase];
#pragma unroll
    for (int i = 0; i < 4; i++) {
        int mrow = m0 + ty * 4 + i;
        float4 v = make_float4(acc[i][0]+bv.x, acc[i][1]+bv.y, acc[i][2]+bv.z, acc[i][3]+bv.w);
        *(float4*)&out[(size_t)mrow * CDIM + obase] = v;
    }
}

// ---------------------------------------------------------------------------
extern "C" void kernel_launch(void* const* d_in, const int* in_sizes, int n_in,
                              void* d_out, int out_size)
{
    const float* x      = (const float*)d_in[0];   // [2,2048,1024]
    const float* w_qkv  = (const float*)d_in[1];   // [8,128,384]
    const float* w_proj = (const float*)d_in[2];   // [8,128,128]
    const float* b_proj = (const float*)d_in[3];   // [1024]
    float* out = (float*)d_out;                    // [2,2048,1024]

    qkv_kernel<<<dim3(64, 6, 8), 256>>>(x, w_qkv);
    attn_kernel<<<dim3(32, 32), 128>>>();
    proj_kernel<<<dim3(64, 2, 8), 256>>>(w_proj, b_proj, out);
}

// round 8
// speedup vs baseline: 2.5710x; 1.1602x over previous
#include <cuda_runtime.h>
#include <cstdint>
#include <stdint.h>
#include <math.h>

// Problem constants
#define BB   2
#define NSEQ 2048
#define CDIM 1024
#define HEADS 16
#define HD   64
#define NG   8
#define KG   128      // Cin per group
#define QKV_OUT 384   // per-group qkv out cols (3*1024/8)

// Scratch (device globals; no allocation allowed)
__device__ float g_q[BB*HEADS*NSEQ*HD];
__device__ float g_k[BB*HEADS*NSEQ*HD];
__device__ float g_v[BB*HEADS*NSEQ*HD];
__device__ float g_attn[BB*NSEQ*CDIM];

// ---------------------------------------------------------------------------
// Shared tf32 mma helpers (fragment mapping verified by Round-4 attention)
// ---------------------------------------------------------------------------
__device__ __forceinline__ uint32_t f2tf32(float x) {
    uint32_t r;
    asm("cvt.rna.tf32.f32 %0, %1;" : "=r"(r) : "f"(x));
    return r;
}

__device__ __forceinline__ void mma_tf32(float* d, const uint32_t* a, uint32_t b0, uint32_t b1) {
    asm volatile(
        "mma.sync.aligned.m16n8k8.row.col.f32.tf32.tf32.f32 "
        "{%0,%1,%2,%3}, {%4,%5,%6,%7}, {%8,%9}, {%0,%1,%2,%3};"
        : "+f"(d[0]), "+f"(d[1]), "+f"(d[2]), "+f"(d[3])
        : "r"(a[0]), "r"(a[1]), "r"(a[2]), "r"(a[3]), "r"(b0), "r"(b1));
}

#define PADA 68   // A-tile row stride (banks 4g+t conflict-free)
#define PADB 72   // B-tile row stride (banks 8t+g conflict-free)

// ---------------------------------------------------------------------------
// QKV grouped GEMM (tf32 tensor cores): per group g:
//   X[4096,128] x W[128,384] -> scatter to q/k/v
// grid (64, 6, 8), block 128 (4 warps). Tile M=64, N=64, K chunks of 64.
// ---------------------------------------------------------------------------
__global__ void __launch_bounds__(128)
qkv_kernel(const float* __restrict__ x, const float* __restrict__ w)
{
    __shared__ float Xs[64 * PADA];   // X tile [row][k]
    __shared__ float Ws[64 * PADB];   // W tile [k][n]

    const int mt = blockIdx.x, ct = blockIdx.y, g = blockIdx.z;
    const int tid  = threadIdx.x;
    const int wp   = tid >> 5;
    const int lane = tid & 31;
    const int gi = lane >> 2;       // 0..7
    const int t  = lane & 3;        // 0..3
    const int q0w = wp * 16;
    const int m0 = mt * 64;

    const float* xg = x + (size_t)m0 * CDIM + g * KG;
    const float* wg = w + (size_t)g * KG * QKV_OUT + ct * 64;

    float s[8][4];
#pragma unroll
    for (int nb = 0; nb < 8; nb++)
#pragma unroll
        for (int j = 0; j < 4; j++) s[nb][j] = 0.f;

    for (int k0 = 0; k0 < KG; k0 += 64) {
        __syncthreads();
#pragma unroll
        for (int i = 0; i < 8; i++) {
            int idx = i * 128 + tid;       // 1024 float4 slots
            int r = idx >> 4;
            int c = (idx & 15) * 4;
            float4 v = *(const float4*)(xg + (size_t)r * CDIM + k0 + c);
            float* d = &Xs[r * PADA + c];
            d[0] = __uint_as_float(f2tf32(v.x));
            d[1] = __uint_as_float(f2tf32(v.y));
            d[2] = __uint_as_float(f2tf32(v.z));
            d[3] = __uint_as_float(f2tf32(v.w));
            float4 u = *(const float4*)(wg + (size_t)(k0 + r) * QKV_OUT + c);
            float* e = &Ws[r * PADB + c];
            e[0] = __uint_as_float(f2tf32(u.x));
            e[1] = __uint_as_float(f2tf32(u.y));
            e[2] = __uint_as_float(f2tf32(u.z));
            e[3] = __uint_as_float(f2tf32(u.w));
        }
        __syncthreads();

        uint32_t qa[8][4];
#pragma unroll
        for (int ks = 0; ks < 8; ks++) {
            qa[ks][0] = __float_as_uint(Xs[(q0w + gi    ) * PADA + ks*8 + t    ]);
            qa[ks][1] = __float_as_uint(Xs[(q0w + gi + 8) * PADA + ks*8 + t    ]);
            qa[ks][2] = __float_as_uint(Xs[(q0w + gi    ) * PADA + ks*8 + t + 4]);
            qa[ks][3] = __float_as_uint(Xs[(q0w + gi + 8) * PADA + ks*8 + t + 4]);
        }

#pragma unroll
        for (int nb = 0; nb < 8; nb++) {
#pragma unroll
            for (int ks = 0; ks < 8; ks++) {
                uint32_t b0 = __float_as_uint(Ws[(ks*8 + t    ) * PADB + nb*8 + gi]);
                uint32_t b1 = __float_as_uint(Ws[(ks*8 + t + 4) * PADB + nb*8 + gi]);
                mma_tf32(s[nb], qa[ks], b0, b1);
            }
        }
    }

    // epilogue: scatter into g_q/g_k/g_v ([B,H,N,D] layout)
    const int seg = g * 6 + ct;           // 64-col segment index in 3072-wide output
    const int tsel = seg >> 4;            // 0=q 1=k 2=v
    const int h = seg & 15;
    const float scale = (tsel == 0) ? 0.125f : 1.f;
    float* dst = (tsel == 0) ? g_q : (tsel == 1) ? g_k : g_v;

    const int m = m0 + q0w + gi;
    const int b = m >> 11, n = m & 2047;
    const size_t base0 = (((size_t)b * HEADS + h) * NSEQ + n    ) * HD;
    const size_t base1 = (((size_t)b * HEADS + h) * NSEQ + n + 8) * HD;
#pragma unroll
    for (int nb = 0; nb < 8; nb++) {
        int c = nb * 8 + 2 * t;
        *(float2*)&dst[base0 + c] = make_float2(s[nb][0] * scale, s[nb][1] * scale);
        *(float2*)&dst[base1 + c] = make_float2(s[nb][2] * scale, s[nb][3] * scale);
    }
}

// ---------------------------------------------------------------------------
// Flash attention with tf32 mma.sync, fp32 softmax.  [unchanged from Round 4]
// grid (32 qtiles, 32 bh), block 128 (4 warps).
// ---------------------------------------------------------------------------
#define PADK 68

__global__ void __launch_bounds__(128)
attn_kernel()
{
    __shared__ float Ks[64 * PADK];   // also used to stage Q in prologue
    __shared__ float Vs[64 * PADK];

    const int qt  = blockIdx.x;
    const int bh  = blockIdx.y;
    const int tid = threadIdx.x;
    const int w   = tid >> 5;
    const int lane = tid & 31;
    const int g = lane >> 2;
    const int t = lane & 3;
    const int q0w = w * 16;

    const float* Qg = g_q + (size_t)bh * NSEQ * HD + (size_t)qt * 64 * HD;
    const float* Kg = g_k + (size_t)bh * NSEQ * HD;
    const float* Vg = g_v + (size_t)bh * NSEQ * HD;

#pragma unroll
    for (int i = 0; i < 8; i++) {
        int idx = i * 128 + tid;
        int r = idx >> 4;
        int c = (idx & 15) * 4;
        float4 v = *(const float4*)(Qg + (size_t)r * HD + c);
        float* d = &Ks[r * PADK + c];
        d[0] = __uint_as_float(f2tf32(v.x));
        d[1] = __uint_as_float(f2tf32(v.y));
        d[2] = __uint_as_float(f2tf32(v.z));
        d[3] = __uint_as_float(f2tf32(v.w));
    }
    __syncthreads();

    uint32_t qa[8][4];
#pragma unroll
    for (int ks = 0; ks < 8; ks++) {
        qa[ks][0] = __float_as_uint(Ks[(q0w + g    ) * PADK + ks*8 + t    ]);
        qa[ks][1] = __float_as_uint(Ks[(q0w + g + 8) * PADK + ks*8 + t    ]);
        qa[ks][2] = __float_as_uint(Ks[(q0w + g    ) * PADK + ks*8 + t + 4]);
        qa[ks][3] = __float_as_uint(Ks[(q0w + g + 8) * PADK + ks*8 + t + 4]);
    }

    float m0 = -1e30f, m1 = -1e30f, l0 = 0.f, l1 = 0.f;
    float o[8][4];
#pragma unroll
    for (int nb = 0; nb < 8; nb++)
#pragma unroll
        for (int j = 0; j < 4; j++) o[nb][j] = 0.f;

    const int srcA = (lane & 28) | (t >> 1);
    const int srcB = srcA + 2;
    const bool odd = (t & 1);

    for (int kt = 0; kt < NSEQ / 64; kt++) {
        __syncthreads();
        const float* Kt = Kg + (size_t)kt * 64 * HD;
        const float* Vt = Vg + (size_t)kt * 64 * HD;
#pragma unroll
        for (int i = 0; i < 8; i++) {
            int idx = i * 128 + tid;
            int r = idx >> 4;
            int c = (idx & 15) * 4;
            float4 v = *(const float4*)(Kt + (size_t)r * HD + c);
            float* d = &Ks[r * PADK + c];
            d[0] = __uint_as_float(f2tf32(v.x));
            d[1] = __uint_as_float(f2tf32(v.y));
            d[2] = __uint_as_float(f2tf32(v.z));
            d[3] = __uint_as_float(f2tf32(v.w));
            float4 u = *(const float4*)(Vt + (size_t)r * HD + c);
            float* e = &Vs[r * PADK + c];
            e[0] = __uint_as_float(f2tf32(u.x));
            e[1] = __uint_as_float(f2tf32(u.y));
            e[2] = __uint_as_float(f2tf32(u.z));
            e[3] = __uint_as_float(f2tf32(u.w));
        }
        __syncthreads();

        float s[8][4];
#pragma unroll
        for (int nb = 0; nb < 8; nb++) {
#pragma unroll
            for (int j = 0; j < 4; j++) s[nb][j] = 0.f;
            const float* kb = &Ks[(nb*8 + g) * PADK];
#pragma unroll
            for (int ks = 0; ks < 8; ks++) {
                uint32_t b0 = __float_as_uint(kb[ks*8 + t]);
                uint32_t b1 = __float_as_uint(kb[ks*8 + t + 4]);
                mma_tf32(s[nb], qa[ks], b0, b1);
            }
        }

        float mx0 = -1e30f, mx1 = -1e30f;
#pragma unroll
        for (int nb = 0; nb < 8; nb++) {
            mx0 = fmaxf(mx0, fmaxf(s[nb][0], s[nb][1]));
            mx1 = fmaxf(mx1, fmaxf(s[nb][2], s[nb][3]));
        }
        mx0 = fmaxf(mx0, __shfl_xor_sync(0xffffffffu, mx0, 1));
        mx0 = fmaxf(mx0, __shfl_xor_sync(0xffffffffu, mx0, 2));
        mx1 = fmaxf(mx1, __shfl_xor_sync(0xffffffffu, mx1, 1));
        mx1 = fmaxf(mx1, __shfl_xor_sync(0xffffffffu, mx1, 2));

        float nm0 = fmaxf(m0, mx0), nm1 = fmaxf(m1, mx1);
        float al0 = __expf(m0 - nm0), al1 = __expf(m1 - nm1);
        m0 = nm0; m1 = nm1;

        float ps0 = 0.f, ps1 = 0.f;
#pragma unroll
        for (int nb = 0; nb < 8; nb++) {
            float p0 = __uint_as_float(f2tf32(__expf(s[nb][0] - nm0)));
            float p1 = __uint_as_float(f2tf32(__expf(s[nb][1] - nm0)));
            float p2 = __uint_as_float(f2tf32(__expf(s[nb][2] - nm1)));
            float p3 = __uint_as_float(f2tf32(__expf(s[nb][3] - nm1)));
            s[nb][0] = p0; s[nb][1] = p1; s[nb][2] = p2; s[nb][3] = p3;
            ps0 += p0 + p1;
            ps1 += p2 + p3;
        }
        ps0 += __shfl_xor_sync(0xffffffffu, ps0, 1);
        ps0 += __shfl_xor_sync(0xffffffffu, ps0, 2);
        ps1 += __shfl_xor_sync(0xffffffffu, ps1, 1);
        ps1 += __shfl_xor_sync(0xffffffffu, ps1, 2);
        l0 = l0 * al0 + ps0;
        l1 = l1 * al1 + ps1;

#pragma unroll
        for (int nb = 0; nb < 8; nb++) {
            o[nb][0] *= al0; o[nb][1] *= al0;
            o[nb][2] *= al1; o[nb][3] *= al1;
        }

#pragma unroll
        for (int ks = 0; ks < 8; ks++) {
            float c0A = __shfl_sync(0xffffffffu, s[ks][0], srcA);
            float c1A = __shfl_sync(0xffffffffu, s[ks][1], srcA);
            float c0B = __shfl_sync(0xffffffffu, s[ks][0], srcB);
            float c1B = __shfl_sync(0xffffffffu, s[ks][1], srcB);
            float c2A = __shfl_sync(0xffffffffu, s[ks][2], srcA);
            float c3A = __shfl_sync(0xffffffffu, s[ks][3], srcA);
            float c2B = __shfl_sync(0xffffffffu, s[ks][2], srcB);
            float c3B = __shfl_sync(0xffffffffu, s[ks][3], srcB);
            uint32_t pa[4];
            pa[0] = __float_as_uint(odd ? c1A : c0A);
            pa[1] = __float_as_uint(odd ? c3A : c2A);
            pa[2] = __float_as_uint(odd ? c1B : c0B);
            pa[3] = __float_as_uint(odd ? c3B : c2B);

            const float* vb0 = &Vs[(ks*8 + t    ) * PADK];
            const float* vb1 = &Vs[(ks*8 + t + 4) * PADK];
#pragma unroll
            for (int nb = 0; nb < 8; nb++) {
                uint32_t b0 = __float_as_uint(vb0[nb*8 + g]);
                uint32_t b1 = __float_as_uint(vb1[nb*8 + g]);
                mma_tf32(o[nb], pa, b0, b1);
            }
        }
    }

    const int b = bh >> 4, h = bh & 15;
    float inv0 = 1.f / l0, inv1 = 1.f / l1;
    int n0 = qt * 64 + q0w + g;
    float* row0 = g_attn + ((size_t)b * NSEQ + n0    ) * CDIM + h * HD;
    float* row1 = g_attn + ((size_t)b * NSEQ + n0 + 8) * CDIM + h * HD;
#pragma unroll
    for (int nb = 0; nb < 8; nb++) {
        int c = nb * 8 + 2 * t;
        *(float2*)&row0[c] = make_float2(o[nb][0] * inv0, o[nb][1] * inv0);
        *(float2*)&row1[c] = make_float2(o[nb][2] * inv1, o[nb][3] * inv1);
    }
}

// ---------------------------------------------------------------------------
// Proj grouped GEMM (tf32 tensor cores): per group g:
//   attn[4096,128] x W[128,128] + bias -> out
// grid (64, 2, 8), block 128.
// ---------------------------------------------------------------------------
__global__ void __launch_bounds__(128)
proj_kernel(const float* __restrict__ w, const float* __restrict__ bias,
            float* __restrict__ out)
{
    __shared__ float Xs[64 * PADA];
    __shared__ float Ws[64 * PADB];

    const int mt = blockIdx.x, ct = blockIdx.y, g = blockIdx.z;
    const int tid  = threadIdx.x;
    const int wp   = tid >> 5;
    const int lane = tid & 31;
    const int gi = lane >> 2;
    const int t  = lane & 3;
    const int q0w = wp * 16;
    const int m0 = mt * 64;

    const float* xg = g_attn + (size_t)m0 * CDIM + g * KG;
    const float* wg = w + (size_t)g * KG * KG + ct * 64;

    float s[8][4];
#pragma unroll
    for (int nb = 0; nb < 8; nb++)
#pragma unroll
        for (int j = 0; j < 4; j++) s[nb][j] = 0.f;

    for (int k0 = 0; k0 < KG; k0 += 64) {
        __syncthreads();
#pragma unroll
        for (int i = 0; i < 8; i++) {
            int idx = i * 128 + tid;
            int r = idx >> 4;
            int c = (idx & 15) * 4;
            float4 v = *(const float4*)(xg + (size_t)r * CDIM + k0 + c);
            float* d = &Xs[r * PADA + c];
            d[0] = __uint_as_float(f2tf32(v.x));
            d[1] = __uint_as_float(f2tf32(v.y));
            d[2] = __uint_as_float(f2tf32(v.z));
            d[3] = __uint_as_float(f2tf32(v.w));
            float4 u = *(const float4*)(wg + (size_t)(k0 + r) * KG + c);
            float* e = &Ws[r * PADB + c];
            e[0] = __uint_as_float(f2tf32(u.x));
            e[1] = __uint_as_float(f2tf32(u.y));
            e[2] = __uint_as_float(f2tf32(u.z));
            e[3] = __uint_as_float(f2tf32(u.w));
        }
        __syncthreads();

        uint32_t qa[8][4];
#pragma unroll
        for (int ks = 0; ks < 8; ks++) {
            qa[ks][0] = __float_as_uint(Xs[(q0w + gi    ) * PADA + ks*8 + t    ]);
            qa[ks][1] = __float_as_uint(Xs[(q0w + gi + 8) * PADA + ks*8 + t    ]);
            qa[ks][2] = __float_as_uint(Xs[(q0w + gi    ) * PADA + ks*8 + t + 4]);
            qa[ks][3] = __float_as_uint(Xs[(q0w + gi + 8) * PADA + ks*8 + t + 4]);
        }

#pragma unroll
        for (int nb = 0; nb < 8; nb++) {
#pragma unroll
            for (int ks = 0; ks < 8; ks++) {
                uint32_t b0 = __float_as_uint(Ws[(ks*8 + t    ) * PADB + nb*8 + gi]);
                uint32_t b1 = __float_as_uint(Ws[(ks*8 + t + 4) * PADB + nb*8 + gi]);
                mma_tf32(s[nb], qa[ks], b0, b1);
            }
        }
    }

    const int obase = g * KG + ct * 64;
    const int m = m0 + q0w + gi;
#pragma unroll
    for (int nb = 0; nb < 8; nb++) {
        int c = nb * 8 + 2 * t;
        float2 bv = *(const float2*)&bias[obase + c];
        *(float2*)&out[(size_t)m * CDIM + obase + c] =
            make_float2(s[nb][0] + bv.x, s[nb][1] + bv.y);
        *(float2*)&out[(size_t)(m + 8) * CDIM + obase + c] =
            make_float2(s[nb][2] + bv.x, s[nb][3] + bv.y);
    }
}

// ---------------------------------------------------------------------------
extern "C" void kernel_launch(void* const* d_in, const int* in_sizes, int n_in,
                              void* d_out, int out_size)
{
    const float* x      = (const float*)d_in[0];   // [2,2048,1024]
    const float* w_qkv  = (const float*)d_in[1];   // [8,128,384]
    const float* w_proj = (const float*)d_in[2];   // [8,128,128]
    const float* b_proj = (const float*)d_in[3];   // [1024]
    float* out = (float*)d_out;                    // [2,2048,1024]

    qkv_kernel<<<dim3(64, 6, 8), 128>>>(x, w_qkv);
    attn_kernel<<<dim3(32, 32), 128>>>();
    proj_kernel<<<dim3(64, 2, 8), 128>>>(w_proj, b_proj, out);
}

// round 10
// speedup vs baseline: 2.8851x; 1.1222x over previous
#include <cuda_runtime.h>
#include <cstdint>
#include <stdint.h>
#include <math.h>

// Problem constants
#define BB   2
#define NSEQ 2048
#define CDIM 1024
#define HEADS 16
#define HD   64
#define NG   8
#define KG   128      // Cin per group
#define QKV_OUT 384   // per-group qkv out cols (3*1024/8)

// Scratch (device globals; no allocation allowed)
__device__ float g_q[BB*HEADS*NSEQ*HD];
__device__ float g_k[BB*HEADS*NSEQ*HD];
__device__ float g_v[BB*HEADS*NSEQ*HD];
__device__ float g_attn[BB*NSEQ*CDIM];

// ---------------------------------------------------------------------------
// Shared tf32 mma helpers
// ---------------------------------------------------------------------------
__device__ __forceinline__ uint32_t f2tf32(float x) {
    uint32_t r;
    asm("cvt.rna.tf32.f32 %0, %1;" : "=r"(r) : "f"(x));
    return r;
}

__device__ __forceinline__ float fexp2(float x) {
    float y;
    asm("ex2.approx.ftz.f32 %0, %1;" : "=f"(y) : "f"(x));
    return y;
}

__device__ __forceinline__ void mma_tf32(float* d, const uint32_t* a, uint32_t b0, uint32_t b1) {
    asm volatile(
        "mma.sync.aligned.m16n8k8.row.col.f32.tf32.tf32.f32 "
        "{%0,%1,%2,%3}, {%4,%5,%6,%7}, {%8,%9}, {%0,%1,%2,%3};"
        : "+f"(d[0]), "+f"(d[1]), "+f"(d[2]), "+f"(d[3])
        : "r"(a[0]), "r"(a[1]), "r"(a[2]), "r"(a[3]), "r"(b0), "r"(b1));
}

// q pre-scale: 1/sqrt(64) * log2(e), so softmax can use ex2 directly
#define QSCALE 0.180336880559151f

#define PADA 36   // GEMM A-tile row stride (K-chunk 32 + pad)
#define PADB 72   // GEMM B-tile row stride

// ---------------------------------------------------------------------------
// QKV grouped GEMM (tf32): X[4096,128] x W[128,384] per group -> q/k/v scatter
// grid (64, 6, 8), block 128. K chunks of 32 (18KB smem, 8 blocks/SM target).
// ---------------------------------------------------------------------------
__global__ void __launch_bounds__(128, 8)
qkv_kernel(const float* __restrict__ x, const float* __restrict__ w)
{
    __shared__ float Xs[64 * PADA];   // [row][k] chunk of 32
    __shared__ float Ws[32 * PADB];   // [k][n]

    const int mt = blockIdx.x, ct = blockIdx.y, g = blockIdx.z;
    const int tid  = threadIdx.x;
    const int wp   = tid >> 5;
    const int lane = tid & 31;
    const int gi = lane >> 2;
    const int t  = lane & 3;
    const int q0w = wp * 16;
    const int m0 = mt * 64;

    const float* xg = x + (size_t)m0 * CDIM + g * KG;
    const float* wg = w + (size_t)g * KG * QKV_OUT + ct * 64;

    float s[8][4];
#pragma unroll
    for (int nb = 0; nb < 8; nb++)
#pragma unroll
        for (int j = 0; j < 4; j++) s[nb][j] = 0.f;

    for (int k0 = 0; k0 < KG; k0 += 32) {
        __syncthreads();
#pragma unroll
        for (int i = 0; i < 4; i++) {
            // X: 64 rows x 32 cols = 512 float4
            int idx = i * 128 + tid;
            int r = idx >> 3;
            int c = (idx & 7) * 4;
            float4 v = *(const float4*)(xg + (size_t)r * CDIM + k0 + c);
            float* d = &Xs[r * PADA + c];
            d[0] = __uint_as_float(f2tf32(v.x));
            d[1] = __uint_as_float(f2tf32(v.y));
            d[2] = __uint_as_float(f2tf32(v.z));
            d[3] = __uint_as_float(f2tf32(v.w));
            // W: 32 rows x 64 cols = 512 float4
            int rw = idx >> 4;
            int cw = (idx & 15) * 4;
            float4 u = *(const float4*)(wg + (size_t)(k0 + rw) * QKV_OUT + cw);
            float* e = &Ws[rw * PADB + cw];
            e[0] = __uint_as_float(f2tf32(u.x));
            e[1] = __uint_as_float(f2tf32(u.y));
            e[2] = __uint_as_float(f2tf32(u.z));
            e[3] = __uint_as_float(f2tf32(u.w));
        }
        __syncthreads();

        uint32_t qa[4][4];
#pragma unroll
        for (int ks = 0; ks < 4; ks++) {
            qa[ks][0] = __float_as_uint(Xs[(q0w + gi    ) * PADA + ks*8 + t    ]);
            qa[ks][1] = __float_as_uint(Xs[(q0w + gi + 8) * PADA + ks*8 + t    ]);
            qa[ks][2] = __float_as_uint(Xs[(q0w + gi    ) * PADA + ks*8 + t + 4]);
            qa[ks][3] = __float_as_uint(Xs[(q0w + gi + 8) * PADA + ks*8 + t + 4]);
        }

#pragma unroll
        for (int nb = 0; nb < 8; nb++) {
#pragma unroll
            for (int ks = 0; ks < 4; ks++) {
                uint32_t b0 = __float_as_uint(Ws[(ks*8 + t    ) * PADB + nb*8 + gi]);
                uint32_t b1 = __float_as_uint(Ws[(ks*8 + t + 4) * PADB + nb*8 + gi]);
                mma_tf32(s[nb], qa[ks], b0, b1);
            }
        }
    }

    // epilogue: scatter into g_q/g_k/g_v ([B,H,N,D] layout)
    const int seg = g * 6 + ct;
    const int tsel = seg >> 4;            // 0=q 1=k 2=v
    const int h = seg & 15;
    const float scale = (tsel == 0) ? QSCALE : 1.f;   // q: 1/8 * log2e folded
    float* dst = (tsel == 0) ? g_q : (tsel == 1) ? g_k : g_v;

    const int m = m0 + q0w + gi;
    const int b = m >> 11, n = m & 2047;
    const size_t base0 = (((size_t)b * HEADS + h) * NSEQ + n    ) * HD;
    const size_t base1 = (((size_t)b * HEADS + h) * NSEQ + n + 8) * HD;
#pragma unroll
    for (int nb = 0; nb < 8; nb++) {
        int c = nb * 8 + 2 * t;
        *(float2*)&dst[base0 + c] = make_float2(s[nb][0] * scale, s[nb][1] * scale);
        *(float2*)&dst[base1 + c] = make_float2(s[nb][2] * scale, s[nb][3] * scale);
    }
}

// ---------------------------------------------------------------------------
// Flash attention, tf32 mma, exp2 softmax, shuffle-free PV via key-order
// permutation, LDS.64 fragment loads via d-order permutation.
// grid (32 qtiles, 32 bh), block 128 (4 warps x 16 q-rows).
// ---------------------------------------------------------------------------
#define PADK 68

__global__ void __launch_bounds__(128)
attn_kernel()
{
    __shared__ float Ks[64 * PADK];   // stages Q in prologue, then K tiles
    __shared__ float Vs[64 * PADK];

    const int qt  = blockIdx.x;
    const int bh  = blockIdx.y;
    const int tid = threadIdx.x;
    const int w   = tid >> 5;
    const int lane = tid & 31;
    const int g = lane >> 2;
    const int t = lane & 3;
    const int q0w = w * 16;

    const float* Qg = g_q + (size_t)bh * NSEQ * HD + (size_t)qt * 64 * HD;
    const float* Kg = g_k + (size_t)bh * NSEQ * HD;
    const float* Vg = g_v + (size_t)bh * NSEQ * HD;

    // ---- prologue: stage Q (tf32-rounded), build A fragments (perm d-order) ----
#pragma unroll
    for (int i = 0; i < 8; i++) {
        int idx = i * 128 + tid;
        int r = idx >> 4;
        int c = (idx & 15) * 4;
        float4 v = *(const float4*)(Qg + (size_t)r * HD + c);
        float* d = &Ks[r * PADK + c];
        d[0] = __uint_as_float(f2tf32(v.x));
        d[1] = __uint_as_float(f2tf32(v.y));
        d[2] = __uint_as_float(f2tf32(v.z));
        d[3] = __uint_as_float(f2tf32(v.w));
    }
    __syncthreads();

    // logical-k order: slot (ks,t) <-> d = 8ks+2t ; slot (ks,t+4) <-> d = 8ks+2t+1
    uint32_t qa[8][4];
#pragma unroll
    for (int ks = 0; ks < 8; ks++) {
        float2 f0 = *(const float2*)&Ks[(q0w + g    ) * PADK + ks*8 + 2*t];
        float2 f1 = *(const float2*)&Ks[(q0w + g + 8) * PADK + ks*8 + 2*t];
        qa[ks][0] = __float_as_uint(f0.x);
        qa[ks][2] = __float_as_uint(f0.y);
        qa[ks][1] = __float_as_uint(f1.x);
        qa[ks][3] = __float_as_uint(f1.y);
    }

    float m0 = -1e30f, m1 = -1e30f, l0 = 0.f, l1 = 0.f;
    float o[8][4];
#pragma unroll
    for (int nb = 0; nb < 8; nb++)
#pragma unroll
        for (int j = 0; j < 4; j++) o[nb][j] = 0.f;

    for (int kt = 0; kt < NSEQ / 64; kt++) {
        __syncthreads();
        const float* Kt = Kg + (size_t)kt * 64 * HD;
        const float* Vt = Vg + (size_t)kt * 64 * HD;
#pragma unroll
        for (int i = 0; i < 8; i++) {
            int idx = i * 128 + tid;
            int r = idx >> 4;
            int c = (idx & 15) * 4;
            float4 v = *(const float4*)(Kt + (size_t)r * HD + c);
            float* d = &Ks[r * PADK + c];
            d[0] = __uint_as_float(f2tf32(v.x));
            d[1] = __uint_as_float(f2tf32(v.y));
            d[2] = __uint_as_float(f2tf32(v.z));
            d[3] = __uint_as_float(f2tf32(v.w));
            float4 u = *(const float4*)(Vt + (size_t)r * HD + c);
            float* e = &Vs[r * PADK + c];
            e[0] = __uint_as_float(f2tf32(u.x));
            e[1] = __uint_as_float(f2tf32(u.y));
            e[2] = __uint_as_float(f2tf32(u.z));
            e[3] = __uint_as_float(f2tf32(u.w));
        }
        __syncthreads();

        // ---- S = Q K^T (d-order permuted; LDS.64 B fragments) ----
        float s[8][4];
#pragma unroll
        for (int nb = 0; nb < 8; nb++) {
#pragma unroll
            for (int j = 0; j < 4; j++) s[nb][j] = 0.f;
            const float* kb = &Ks[(nb*8 + g) * PADK];
#pragma unroll
            for (int ks = 0; ks < 8; ks++) {
                float2 f = *(const float2*)&kb[ks*8 + 2*t];
                mma_tf32(s[nb], qa[ks], __float_as_uint(f.x), __float_as_uint(f.y));
            }
        }

        // ---- online softmax in exp2 domain (S already scaled by log2e) ----
        float mx0 = -1e30f, mx1 = -1e30f;
#pragma unroll
        for (int nb = 0; nb < 8; nb++) {
            mx0 = fmaxf(mx0, fmaxf(s[nb][0], s[nb][1]));
            mx1 = fmaxf(mx1, fmaxf(s[nb][2], s[nb][3]));
        }
        mx0 = fmaxf(mx0, __shfl_xor_sync(0xffffffffu, mx0, 1));
        mx0 = fmaxf(mx0, __shfl_xor_sync(0xffffffffu, mx0, 2));
        mx1 = fmaxf(mx1, __shfl_xor_sync(0xffffffffu, mx1, 1));
        mx1 = fmaxf(mx1, __shfl_xor_sync(0xffffffffu, mx1, 2));

        float nm0 = fmaxf(m0, mx0), nm1 = fmaxf(m1, mx1);
        float al0 = fexp2(m0 - nm0), al1 = fexp2(m1 - nm1);
        m0 = nm0; m1 = nm1;

        float ps0 = 0.f, ps1 = 0.f;
#pragma unroll
        for (int nb = 0; nb < 8; nb++) {
            float p0 = __uint_as_float(f2tf32(fexp2(s[nb][0] - nm0)));
            float p1 = __uint_as_float(f2tf32(fexp2(s[nb][1] - nm0)));
            float p2 = __uint_as_float(f2tf32(fexp2(s[nb][2] - nm1)));
            float p3 = __uint_as_float(f2tf32(fexp2(s[nb][3] - nm1)));
            s[nb][0] = p0; s[nb][1] = p1; s[nb][2] = p2; s[nb][3] = p3;
            ps0 += p0 + p1;
            ps1 += p2 + p3;
        }
        ps0 += __shfl_xor_sync(0xffffffffu, ps0, 1);
        ps0 += __shfl_xor_sync(0xffffffffu, ps0, 2);
        ps1 += __shfl_xor_sync(0xffffffffu, ps1, 1);
        ps1 += __shfl_xor_sync(0xffffffffu, ps1, 2);
        l0 = l0 * al0 + ps0;
        l1 = l1 * al1 + ps1;

#pragma unroll
        for (int nb = 0; nb < 8; nb++) {
            o[nb][0] *= al0; o[nb][1] *= al0;
            o[nb][2] *= al1; o[nb][3] *= al1;
        }

        // ---- O += P V : key-order permutation makes C-frag == A-frag ----
        // A slot (ks,t) <-> key 8ks+2t ; slot (ks,t+4) <-> key 8ks+2t+1
#pragma unroll
        for (int ks = 0; ks < 8; ks++) {
            uint32_t pa[4];
            pa[0] = __float_as_uint(s[ks][0]);   // P[g   ][8ks+2t  ]
            pa[1] = __float_as_uint(s[ks][2]);   // P[g+8 ][8ks+2t  ]
            pa[2] = __float_as_uint(s[ks][1]);   // P[g   ][8ks+2t+1]
            pa[3] = __float_as_uint(s[ks][3]);   // P[g+8 ][8ks+2t+1]

            const float* vb0 = &Vs[(ks*8 + 2*t    ) * PADK];
            const float* vb1 = &Vs[(ks*8 + 2*t + 1) * PADK];
#pragma unroll
            for (int nb = 0; nb < 8; nb++) {
                uint32_t b0 = __float_as_uint(vb0[nb*8 + g]);
                uint32_t b1 = __float_as_uint(vb1[nb*8 + g]);
                mma_tf32(o[nb], pa, b0, b1);
            }
        }
    }

    // ---- epilogue ----
    const int b = bh >> 4, h = bh & 15;
    float inv0 = 1.f / l0, inv1 = 1.f / l1;
    int n0 = qt * 64 + q0w + g;
    float* row0 = g_attn + ((size_t)b * NSEQ + n0    ) * CDIM + h * HD;
    float* row1 = g_attn + ((size_t)b * NSEQ + n0 + 8) * CDIM + h * HD;
#pragma unroll
    for (int nb = 0; nb < 8; nb++) {
        int c = nb * 8 + 2 * t;
        *(float2*)&row0[c] = make_float2(o[nb][0] * inv0, o[nb][1] * inv0);
        *(float2*)&row1[c] = make_float2(o[nb][2] * inv1, o[nb][3] * inv1);
    }
}

// ---------------------------------------------------------------------------
// Proj grouped GEMM (tf32): attn[4096,128] x W[128,128] + bias -> out
// grid (64, 2, 8), block 128. K chunks of 32.
// ---------------------------------------------------------------------------
__global__ void __launch_bounds__(128, 8)
proj_kernel(const float* __restrict__ w, const float* __restrict__ bias,
            float* __restrict__ out)
{
    __shared__ float Xs[64 * PADA];
    __shared__ float Ws[32 * PADB];

    const int mt = blockIdx.x, ct = blockIdx.y, g = blockIdx.z;
    const int tid  = threadIdx.x;
    const int wp   = tid >> 5;
    const int lane = tid & 31;
    const int gi = lane >> 2;
    const int t  = lane & 3;
    const int q0w = wp * 16;
    const int m0 = mt * 64;

    const float* xg = g_attn + (size_t)m0 * CDIM + g * KG;
    const float* wg = w + (size_t)g * KG * KG + ct * 64;

    float s[8][4];
#pragma unroll
    for (int nb = 0; nb < 8; nb++)
#pragma unroll
        for (int j = 0; j < 4; j++) s[nb][j] = 0.f;

    for (int k0 = 0; k0 < KG; k0 += 32) {
        __syncthreads();
#pragma unroll
        for (int i = 0; i < 4; i++) {
            int idx = i * 128 + tid;
            int r = idx >> 3;
            int c = (idx & 7) * 4;
            float4 v = *(const float4*)(xg + (size_t)r * CDIM + k0 + c);
            float* d = &Xs[r * PADA + c];
            d[0] = __uint_as_float(f2tf32(v.x));
            d[1] = __uint_as_float(f2tf32(v.y));
            d[2] = __uint_as_float(f2tf32(v.z));
            d[3] = __uint_as_float(f2tf32(v.w));
            int rw = idx >> 4;
            int cw = (idx & 15) * 4;
            float4 u = *(const float4*)(wg + (size_t)(k0 + rw) * KG + cw);
            float* e = &Ws[rw * PADB + cw];
            e[0] = __uint_as_float(f2tf32(u.x));
            e[1] = __uint_as_float(f2tf32(u.y));
            e[2] = __uint_as_float(f2tf32(u.z));
            e[3] = __uint_as_float(f2tf32(u.w));
        }
        __syncthreads();

        uint32_t qa[4][4];
#pragma unroll
        for (int ks = 0; ks < 4; ks++) {
            qa[ks][0] = __float_as_uint(Xs[(q0w + gi    ) * PADA + ks*8 + t    ]);
            qa[ks][1] = __float_as_uint(Xs[(q0w + gi + 8) * PADA + ks*8 + t    ]);
            qa[ks][2] = __float_as_uint(Xs[(q0w + gi    ) * PADA + ks*8 + t + 4]);
            qa[ks][3] = __float_as_uint(Xs[(q0w + gi + 8) * PADA + ks*8 + t + 4]);
        }

#pragma unroll
        for (int nb = 0; nb < 8; nb++) {
#pragma unroll
            for (int ks = 0; ks < 4; ks++) {
                uint32_t b0 = __float_as_uint(Ws[(ks*8 + t    ) * PADB + nb*8 + gi]);
                uint32_t b1 = __float_as_uint(Ws[(ks*8 + t + 4) * PADB + nb*8 + gi]);
                mma_tf32(s[nb], qa[ks], b0, b1);
            }
        }
    }

    const int obase = g * KG + ct * 64;
    const int m = m0 + q0w + gi;
#pragma unroll
    for (int nb = 0; nb < 8; nb++) {
        int c = nb * 8 + 2 * t;
        float2 bv = *(const float2*)&bias[obase + c];
        *(float2*)&out[(size_t)m * CDIM + obase + c] =
            make_float2(s[nb][0] + bv.x, s[nb][1] + bv.y);
        *(float2*)&out[(size_t)(m + 8) * CDIM + obase + c] =
            make_float2(s[nb][2] + bv.x, s[nb][3] + bv.y);
    }
}

// ---------------------------------------------------------------------------
extern "C" void kernel_launch(void* const* d_in, const int* in_sizes, int n_in,
                              void* d_out, int out_size)
{
    const float* x      = (const float*)d_in[0];   // [2,2048,1024]
    const float* w_qkv  = (const float*)d_in[1];   // [8,128,384]
    const float* w_proj = (const float*)d_in[2];   // [8,128,128]
    const float* b_proj = (const float*)d_in[3];   // [1024]
    float* out = (float*)d_out;                    // [2,2048,1024]

    qkv_kernel<<<dim3(64, 6, 8), 128>>>(x, w_qkv);
    attn_kernel<<<dim3(32, 32), 128>>>();
    proj_kernel<<<dim3(64, 2, 8), 128>>>(w_proj, b_proj, out);
}